// round 2
// baseline (speedup 1.0000x reference)
#include <cuda_runtime.h>
#include <math.h>

#define T_LEN 8192
#define RADIUS 32              // G(x)=0 beyond |x|=32 to ~1e-15 (sigma_max=4)
#define NTAPS (RADIUS + 1)     // one-sided taps incl. x=0
#define BLOCKS 64              // 64 * 128 = 8192 outputs, all co-resident
#define INV_SQRT_2PI 0.39894228f
#define NOISE_SIGMA 0.01f

__device__ float g_pmin[BLOCKS];
__device__ float g_pmax[BLOCKS];
__device__ unsigned g_bar1 = 0;
__device__ unsigned g_bar2 = 0;

__device__ __forceinline__ float warp_sum(float v) {
    #pragma unroll
    for (int o = 16; o > 0; o >>= 1) v += __shfl_xor_sync(0xffffffffu, v, o);
    return v;
}
__device__ __forceinline__ float warp_max(float v) {
    #pragma unroll
    for (int o = 16; o > 0; o >>= 1) v = fmaxf(v, __shfl_xor_sync(0xffffffffu, v, o));
    return v;
}
__device__ __forceinline__ float warp_min(float v) {
    #pragma unroll
    for (int o = 16; o > 0; o >>= 1) v = fminf(v, __shfl_xor_sync(0xffffffffu, v, o));
    return v;
}

// Single fused kernel: softmax + combined-Gaussian table + truncated conv +
// noise + global min/max (software grid barrier) + normalize.
// 64 blocks x 128 threads. Grid barrier is safe: all 64 blocks are resident
// in wave 1 (148 SMs, <18KB smem, 128 threads). Counters self-reset so the
// kernel is graph-replayable.
__global__ void __launch_bounds__(128, 1)
k_fused(const float* __restrict__ X,
        const float* __restrict__ weight,
        const float* __restrict__ sigma_min,
        const float* __restrict__ sigma_max,
        const float* __restrict__ noise,
        float* __restrict__ out) {
    __shared__ float tileG[NTAPS * 128];   // [tap][d] partial Gaussian values
    __shared__ float sG[NTAPS];            // reduced combined kernel, taps 0..32
    __shared__ float sM[192];              // mask window [base-33, base+158]
    __shared__ float sred[4];
    __shared__ float slo[2], shi[2];

    const int tid = threadIdx.x;           // == d (sigma index)
    const int wid = tid >> 5;
    const int lid = tid & 31;
    const int base = blockIdx.x * 128;
    const int t = base + tid;

    // --- start long-latency global loads early ---
    float nz = NOISE_SIGMA * noise[t];
    #pragma unroll
    for (int i = tid; i < 192; i += 128) {
        int gi = base - 33 + i;
        sM[i] = (gi >= 0 && gi < T_LEN && X[gi] > 0.5f) ? 1.0f : 0.0f;
    }
    float w = weight[tid];
    float smn = sigma_min[0];
    float smx = sigma_max[0];

    // --- softmax over the 128 weights (block-wide) ---
    float m = warp_max(w);
    if (lid == 0) sred[wid] = m;
    __syncthreads();
    float bm = fmaxf(fmaxf(sred[0], sred[1]), fmaxf(sred[2], sred[3]));
    __syncthreads();
    float e = expf(w - bm);
    float s = warp_sum(e);
    if (lid == 0) sred[wid] = s;
    __syncthreads();
    float p = e / (sred[0] + sred[1] + sred[2] + sred[3]);

    // --- per-sigma Gaussian via multiplicative recurrence (3 expf total) ---
    float sig = fabsf(smn + (float)tid * (smx - smn) * (1.0f / 127.0f));
    float cc  = 0.5f / (sig * sig);
    float g   = p * (INV_SQRT_2PI / sig);   // value at x = 0
    float e1  = expf(-cc);                  // ratio step seed
    float e2  = e1 * e1;
    float f   = e1;                         // exp(-c(2x+1)) for x=0
    #pragma unroll
    for (int x = 0; x < NTAPS; ++x) {
        tileG[x * 128 + tid] = g;           // conflict-free (consecutive tid)
        g *= f;
        f *= e2;
    }
    __syncthreads();

    // --- reduce over d: each warp owns taps wid, wid+4, ... ---
    #pragma unroll
    for (int tap = wid; tap < NTAPS; tap += 4) {
        const float* row = &tileG[tap * 128];
        float v = row[lid] + row[lid + 32] + row[lid + 64] + row[lid + 96];
        v = warp_sum(v);
        if (lid == 0) sG[tap] = v;
    }
    __syncthreads();

    // --- truncated symmetric convolution: psedu[t] = sum_x G(|x|) m[t-1-x] ---
    const float* mm = &sM[tid + 32];        // mm[d] = mask[t-1+d]
    float acc = nz;
    acc = fmaf(sG[0], mm[0], acc);
    #pragma unroll
    for (int x = 1; x < NTAPS; ++x)
        acc = fmaf(sG[x], mm[-x] + mm[x], acc);

    // --- block min/max, publish partials ---
    float mn = warp_min(acc);
    float mx = warp_max(acc);
    if (lid == 0) { slo[0] = 0.0f; sred[wid] = mn; }   // reuse sred for mins
    __syncthreads();
    float bmin = fminf(fminf(sred[0], sred[1]), fminf(sred[2], sred[3]));
    __syncthreads();
    if (lid == 0) sred[wid] = mx;
    __syncthreads();
    float bmax = fmaxf(fmaxf(sred[0], sred[1]), fmaxf(sred[2], sred[3]));

    if (tid == 0) {
        g_pmin[blockIdx.x] = bmin;
        g_pmax[blockIdx.x] = bmax;
        __threadfence();                    // release partials
        atomicAdd(&g_bar1, 1u);
        // spin until all 64 blocks have published (volatile -> bypass L1)
        while (*((volatile unsigned*)&g_bar1) < BLOCKS) { }
    }
    __syncthreads();
    __threadfence();                        // acquire

    // --- every block redundantly reduces the 64 partials ---
    float lo = INFINITY, hi = -INFINITY;
    if (tid < BLOCKS) {
        lo = __ldcg(&g_pmin[tid]);
        hi = __ldcg(&g_pmax[tid]);
        lo = warp_min(lo);
        hi = warp_max(hi);
        if (lid == 0) { slo[wid] = lo; shi[wid] = hi; }
    }
    __syncthreads();
    float L = fminf(slo[0], slo[1]);
    float H = fmaxf(shi[0], shi[1]);

    out[t] = (acc - L) * (1.0f / (H - L));

    // --- last block to finish resets the barrier counters for graph replay ---
    if (tid == 0) {
        unsigned done = atomicAdd(&g_bar2, 1u);
        if (done == BLOCKS - 1) {
            g_bar1 = 0;
            g_bar2 = 0;
            __threadfence();
        }
    }
}

extern "C" void kernel_launch(void* const* d_in, const int* in_sizes, int n_in,
                              void* d_out, int out_size) {
    const float* X     = (const float*)d_in[0];
    const float* wgt   = (const float*)d_in[1];
    const float* smin  = (const float*)d_in[2];
    const float* smax  = (const float*)d_in[3];
    const float* noise = (const float*)d_in[4];
    float* out = (float*)d_out;

    k_fused<<<BLOCKS, 128>>>(X, wgt, smin, smax, noise, out);
}

// round 3
// speedup vs baseline: 1.2610x; 1.2610x over previous
#include <cuda_runtime.h>
#include <math.h>

#define T_LEN 8192
#define RADIUS 20              // tail beyond 20: exp(-400/32)~4e-6 * tiny coef -> <1e-8 rel
#define NTAPS (RADIUS + 1)     // one-sided taps incl. x=0
#define BLOCKS 64              // 64 * 128 = 8192 outputs, all co-resident in wave 1
#define MWIN (128 + 2 * RADIUS + 2)   // mask window size (170)
#define INV_SQRT_2PI 0.39894228f
#define NOISE_SIGMA 0.01f

// Barrier / reduction state. Zero-init at load; epilogue restores these exact
// values every call so the kernel is graph-replayable.
__device__ unsigned g_lo = 0xFFFFFFFFu;   // encoded-min identity
__device__ unsigned g_hi = 0u;            // encoded-max identity
__device__ unsigned g_ctr = 0u;
__device__ unsigned g_ctr2 = 0u;
__device__ unsigned long long g_pub = 0ull;  // packed {lo,hi}; nonzero == ready

__device__ __forceinline__ float warp_sum(float v) {
    #pragma unroll
    for (int o = 16; o > 0; o >>= 1) v += __shfl_xor_sync(0xffffffffu, v, o);
    return v;
}

// order-preserving float<->uint encoding (unsigned ascending == float ascending)
__device__ __forceinline__ unsigned enc_f(float f) {
    unsigned u = __float_as_uint(f);
    return (u & 0x80000000u) ? ~u : (u | 0x80000000u);
}
__device__ __forceinline__ float dec_f(unsigned e) {
    unsigned u = (e & 0x80000000u) ? (e ^ 0x80000000u) : ~e;
    return __uint_as_float(u);
}

__global__ void __launch_bounds__(128, 1)
k_fused(const float* __restrict__ X,
        const float* __restrict__ weight,
        const float* __restrict__ sigma_min,
        const float* __restrict__ sigma_max,
        const float* __restrict__ noise,
        float* __restrict__ out) {
    __shared__ float tileG[NTAPS * 128];   // [tap][d]
    __shared__ float sG[NTAPS];            // combined kernel, taps 0..RADIUS
    __shared__ float sM[MWIN];             // mask window [base-RADIUS-1, ...)
    __shared__ float sred[4];
    __shared__ float smn[4], smx[4];

    const int tid = threadIdx.x;           // == d (sigma index)
    const int wid = tid >> 5;
    const int lid = tid & 31;
    const int base = blockIdx.x * 128;
    const int t = base + tid;

    // ---- issue all long-latency loads up front ----
    float nz  = NOISE_SIGMA * noise[t];
    float w   = weight[tid];
    float smn_v = sigma_min[0];
    float smx_v = sigma_max[0];
    #pragma unroll
    for (int i = tid; i < MWIN; i += 128) {
        int gi = base - (RADIUS + 1) + i;
        sM[i] = (gi >= 0 && gi < T_LEN && X[gi] > 0.5f) ? 1.0f : 0.0f;
    }

    // ---- softmax sum (no max-subtract; exact for |w| < ~80) ----
    float e = expf(w);
    float s = warp_sum(e);
    if (lid == 0) sred[wid] = s;

    // ---- Gaussian recurrence into registers, overlapped with the reduction ----
    float sig = fabsf(smn_v + (float)tid * (smx_v - smn_v) * (1.0f / 127.0f));
    float cc  = 0.5f / (sig * sig);
    float g0  = INV_SQRT_2PI / sig;        // unscaled value at x=0
    float e1  = expf(-cc);
    float e2  = e1 * e1;
    float gv[NTAPS];
    {
        float g = g0, f = e1;
        #pragma unroll
        for (int x = 0; x < NTAPS; ++x) { gv[x] = g; g *= f; f *= e2; }
    }

    __syncthreads();
    float p = e / (sred[0] + sred[1] + sred[2] + sred[3]);

    #pragma unroll
    for (int x = 0; x < NTAPS; ++x)
        tileG[x * 128 + tid] = p * gv[x];   // conflict-free
    __syncthreads();

    // ---- reduce over d: warp `wid` owns taps wid, wid+4, ... ----
    #pragma unroll
    for (int tap = wid; tap < NTAPS; tap += 4) {
        const float* row = &tileG[tap * 128];
        float v = row[lid] + row[lid + 32] + row[lid + 64] + row[lid + 96];
        v = warp_sum(v);
        if (lid == 0) sG[tap] = v;
    }
    __syncthreads();

    // ---- truncated symmetric conv: psedu[t] = sum_x G(|x|) mask[t-1-x] ----
    const float* mm = &sM[tid + RADIUS];    // mm[d] = mask[t-1+d]
    float acc = fmaf(sG[0], mm[0], nz);
    #pragma unroll
    for (int x = 1; x < NTAPS; ++x)
        acc = fmaf(sG[x], mm[-x] + mm[x], acc);

    // ---- block min/max (interleaved independent shuffle chains) ----
    float mn = acc, mx = acc;
    #pragma unroll
    for (int o = 16; o > 0; o >>= 1) {
        mn = fminf(mn, __shfl_xor_sync(0xffffffffu, mn, o));
        mx = fmaxf(mx, __shfl_xor_sync(0xffffffffu, mx, o));
    }
    if (lid == 0) { smn[wid] = mn; smx[wid] = mx; }
    __syncthreads();

    // ---- grid min/max via atomics + last-arriver broadcast ----
    if (tid == 0) {
        float bmin = fminf(fminf(smn[0], smn[1]), fminf(smn[2], smn[3]));
        float bmax = fmaxf(fmaxf(smx[0], smx[1]), fmaxf(smx[2], smx[3]));
        atomicMin(&g_lo, enc_f(bmin));
        atomicMax(&g_hi, enc_f(bmax));
        __threadfence();
        unsigned old = atomicAdd(&g_ctr, 1u);
        if (old == BLOCKS - 1) {            // last block: broadcast {lo,hi} + flag
            __threadfence();
            unsigned lo = *((volatile unsigned*)&g_lo);
            unsigned hi = *((volatile unsigned*)&g_hi);
            unsigned long long pk = ((unsigned long long)hi << 32) | lo;
            *((volatile unsigned long long*)&g_pub) = pk;  // nonzero (lo!=0 always)
        }
    }

    // every thread polls the packed word; data arrives with the flag
    unsigned long long pk;
    do { pk = *((volatile unsigned long long*)&g_pub); } while (pk == 0ull);
    float L = dec_f((unsigned)pk);
    float H = dec_f((unsigned)(pk >> 32));

    out[t] = (acc - L) * (1.0f / (H - L));

    // ---- reset for next graph replay (after ALL threads passed the poll) ----
    __syncthreads();
    if (tid == 0) {
        unsigned done = atomicAdd(&g_ctr2, 1u);
        if (done == BLOCKS - 1) {
            g_pub = 0ull;
            g_lo  = 0xFFFFFFFFu;
            g_hi  = 0u;
            g_ctr = 0u;
            g_ctr2 = 0u;
            __threadfence();
        }
    }
}

extern "C" void kernel_launch(void* const* d_in, const int* in_sizes, int n_in,
                              void* d_out, int out_size) {
    const float* X     = (const float*)d_in[0];
    const float* wgt   = (const float*)d_in[1];
    const float* smin  = (const float*)d_in[2];
    const float* smax  = (const float*)d_in[3];
    const float* noise = (const float*)d_in[4];
    float* out = (float*)d_out;

    k_fused<<<BLOCKS, 128>>>(X, wgt, smin, smax, noise, out);
}